// round 12
// baseline (speedup 1.0000x reference)
#include <cuda_runtime.h>
#include <math.h>

// Problem dims
#define Bq      32
#define Dq      512
#define Hq      1024
#define FOURH   4096
#define KTOT    1536            // H + D combined reduction dim
#define KSPLIT  16
#define KCHUNK  (KTOT / KSPLIT) // 96
#define PSPLIT  64              // plastic i-splits per batch
#define PCHUNK  (Hq / PSPLIT)   // 16

#define GB      8               // batches per group
#define NGRP    (Bq / GB)       // 4 groups
#define NPL_G   (GB * PSPLIT)   // 512 plastic blocks per group
#define NHB_G   (GB * Hq / 4)   // 2048 hebb blocks per group
#define NGEMM   (32 * KSPLIT)   // 512 gemm blocks

// Scratch (static __device__ — no allocation)
__device__ float g_part[KSPLIT][Bq * FOURH];        // GEMM partials (8 MB)
__device__ float g_plastic_part[Bq * PSPLIT * Hq];  // plastic partials (8 MB)
__device__ float g_tanhg[Bq * Hq];                  // tanh(cell gate) (128 KB)

// ---------------------------------------------------------------------------
// Plastic body (R10-proven 2-row streaming): block p covers (b, sp).
// partial[b,sp,h] = sum_{i in 16-chunk sp} h0[b,i]*alpha[i,h]*Hebb0[b,i,h]
// ---------------------------------------------------------------------------
__device__ __forceinline__
void plastic_body(int p, int b0, const float* __restrict__ h0,
                  const float* __restrict__ alpha, const float* __restrict__ Hebb0)
{
    const int b  = b0 + (p >> 6);
    const int sp = p & 63;
    const int i0 = sp * PCHUNK;
    const int t  = threadIdx.x;

    const float4* Ap  = (const float4*)(alpha + (size_t)i0 * Hq) + t;
    const float4* Hp  = (const float4*)(Hebb0 + ((size_t)b * Hq + i0) * Hq) + t;
    const float*  h0p = h0 + b * Hq + i0;

    float4 acc = make_float4(0.f, 0.f, 0.f, 0.f);
#pragma unroll 1
    for (int i = 0; i < PCHUNK; i += 2) {
        float4 a0 = Ap[(size_t)(i + 0) * 256];
        float4 v0 = Hp[(size_t)(i + 0) * 256];
        float4 a1 = Ap[(size_t)(i + 1) * 256];
        float4 v1 = Hp[(size_t)(i + 1) * 256];
        float s0 = h0p[i + 0];
        float s1 = h0p[i + 1];
        acc.x = fmaf(s0, a0.x * v0.x, acc.x);
        acc.y = fmaf(s0, a0.y * v0.y, acc.y);
        acc.z = fmaf(s0, a0.z * v0.z, acc.z);
        acc.w = fmaf(s0, a0.w * v0.w, acc.w);
        acc.x = fmaf(s1, a1.x * v1.x, acc.x);
        acc.y = fmaf(s1, a1.y * v1.y, acc.y);
        acc.z = fmaf(s1, a1.z * v1.z, acc.z);
        acc.w = fmaf(s1, a1.w * v1.w, acc.w);
    }
    ((float4*)(g_plastic_part + (size_t)(b * PSPLIT + sp) * Hq))[t] = acc;
}

// ---------------------------------------------------------------------------
// Hebb body (R8-proven 4-row): local block lb in [0, NHB_G), group g.
// Hebb1[b,h,i] = clip(Hebb0[b,h,i] + eta*h0[b,h]*tanh_g[b,i], -1, 1)
// Reads hit L2 (slice streamed by plastic one launch earlier); ldcs demotes.
// ---------------------------------------------------------------------------
__device__ __forceinline__
void hebb_body(int lb, int g, const float* __restrict__ Hebb0,
               const float* __restrict__ h0, const float* __restrict__ eta,
               float* __restrict__ HebbOut)
{
    const int r0 = g * (GB * Hq) + lb * 4;
    const int b  = r0 >> 10;
    const float e = eta[0];
    const int t = threadIdx.x;

    float4 tv = ((const float4*)(g_tanhg + (size_t)b * Hq))[t];

    const float4* in4 = (const float4*)(Hebb0   + (size_t)r0 * Hq) + t;
    float4*       o4  = (float4*)      (HebbOut + (size_t)r0 * Hq) + t;

    float c0f = e * h0[r0 + 0];
    float c1f = e * h0[r0 + 1];
    float c2f = e * h0[r0 + 2];
    float c3f = e * h0[r0 + 3];

    float4 v0 = __ldcs(in4 + 0 * 256);
    float4 v1 = __ldcs(in4 + 1 * 256);
    float4 v2 = __ldcs(in4 + 2 * 256);
    float4 v3 = __ldcs(in4 + 3 * 256);

    float4 o;
    o.x = fminf(1.f, fmaxf(-1.f, fmaf(c0f, tv.x, v0.x)));
    o.y = fminf(1.f, fmaxf(-1.f, fmaf(c0f, tv.y, v0.y)));
    o.z = fminf(1.f, fmaxf(-1.f, fmaf(c0f, tv.z, v0.z)));
    o.w = fminf(1.f, fmaxf(-1.f, fmaf(c0f, tv.w, v0.w)));
    __stcs(o4 + 0 * 256, o);
    o.x = fminf(1.f, fmaxf(-1.f, fmaf(c1f, tv.x, v1.x)));
    o.y = fminf(1.f, fmaxf(-1.f, fmaf(c1f, tv.y, v1.y)));
    o.z = fminf(1.f, fmaxf(-1.f, fmaf(c1f, tv.z, v1.z)));
    o.w = fminf(1.f, fmaxf(-1.f, fmaf(c1f, tv.w, v1.w)));
    __stcs(o4 + 1 * 256, o);
    o.x = fminf(1.f, fmaxf(-1.f, fmaf(c2f, tv.x, v2.x)));
    o.y = fminf(1.f, fmaxf(-1.f, fmaf(c2f, tv.y, v2.y)));
    o.z = fminf(1.f, fmaxf(-1.f, fmaf(c2f, tv.z, v2.z)));
    o.w = fminf(1.f, fmaxf(-1.f, fmaf(c2f, tv.w, v2.w)));
    __stcs(o4 + 2 * 256, o);
    o.x = fminf(1.f, fmaxf(-1.f, fmaf(c3f, tv.x, v3.x)));
    o.y = fminf(1.f, fmaxf(-1.f, fmaf(c3f, tv.y, v3.y)));
    o.z = fminf(1.f, fmaxf(-1.f, fmaf(c3f, tv.z, v3.z)));
    o.w = fminf(1.f, fmaxf(-1.f, fmaf(c3f, tv.w, v3.w)));
    __stcs(o4 + 3 * 256, o);
}

// ---------------------------------------------------------------------------
// K_A: gemm (512 blocks) + plastic group 0 (512 blocks)
// ---------------------------------------------------------------------------
__global__ __launch_bounds__(256)
void k_A(const float* __restrict__ x,  const float* __restrict__ h0,
         const float* __restrict__ Wh, const float* __restrict__ Wx,
         const float* __restrict__ alpha, const float* __restrict__ Hebb0)
{
    if (blockIdx.x >= NGEMM) {
        plastic_body(blockIdx.x - NGEMM, 0, h0, alpha, Hebb0);
        return;
    }
    // ---------------- gemm partials (R10-proven) ----------------
    __shared__ float Ws[32][128];
    __shared__ float As[32][33];

    const int jt  = blockIdx.x & 31;
    const int ks  = blockIdx.x >> 5;
    const int tid = threadIdx.x;
    const int tj  = tid & 31;
    const int tb  = tid >> 5;

    float acc[4][4];
#pragma unroll
    for (int i = 0; i < 4; i++)
#pragma unroll
        for (int j = 0; j < 4; j++) acc[i][j] = 0.f;

    const int k0base = ks * KCHUNK;
    const int jbase  = jt * 128;

    const float4* Wh4 = (const float4*)Wh;
    const float4* Wx4 = (const float4*)Wx;

    for (int t = 0; t < KCHUNK / 32; t++) {
        const int k0 = k0base + t * 32;
        __syncthreads();
#pragma unroll
        for (int s = 0; s < 4; s++) {
            int lin = s * 256 + tid;
            int kk = lin >> 5, j4 = lin & 31;
            int k = k0 + kk;
            float4 w = (k < Hq) ? Wh4[(size_t)k * 1024 + (jbase >> 2) + j4]
                                : Wx4[(size_t)(k - Hq) * 1024 + (jbase >> 2) + j4];
            *(float4*)&Ws[kk][j4 * 4] = w;
        }
#pragma unroll
        for (int s = 0; s < 4; s++) {
            int lin = s * 256 + tid;
            int bb = lin >> 5, kk = lin & 31;
            int k = k0 + kk;
            As[bb][kk] = (k < Hq) ? h0[bb * Hq + k] : x[bb * Dq + (k - Hq)];
        }
        __syncthreads();
#pragma unroll
        for (int kk = 0; kk < 32; kk++) {
            float4 w = *(const float4*)&Ws[kk][tj * 4];
            float a0 = As[tb * 4 + 0][kk];
            float a1 = As[tb * 4 + 1][kk];
            float a2 = As[tb * 4 + 2][kk];
            float a3 = As[tb * 4 + 3][kk];
            acc[0][0] += a0*w.x; acc[0][1] += a0*w.y; acc[0][2] += a0*w.z; acc[0][3] += a0*w.w;
            acc[1][0] += a1*w.x; acc[1][1] += a1*w.y; acc[1][2] += a1*w.z; acc[1][3] += a1*w.w;
            acc[2][0] += a2*w.x; acc[2][1] += a2*w.y; acc[2][2] += a2*w.z; acc[2][3] += a2*w.w;
            acc[3][0] += a3*w.x; acc[3][1] += a3*w.y; acc[3][2] += a3*w.z; acc[3][3] += a3*w.w;
        }
    }

    float* outp = g_part[ks];
#pragma unroll
    for (int bb = 0; bb < 4; bb++) {
        int b = tb * 4 + bb;
        int base = b * FOURH + jbase + tj * 4;
        *(float4*)&outp[base] = make_float4(acc[bb][0], acc[bb][1], acc[bb][2], acc[bb][3]);
    }
}

// ---------------------------------------------------------------------------
// K_hp: plastic group g+1 (blocks [0,512)) + hebb group g (blocks [512,2560))
// ---------------------------------------------------------------------------
__global__ __launch_bounds__(256)
void k_hp(const float* __restrict__ h0, const float* __restrict__ alpha,
          const float* __restrict__ Hebb0, const float* __restrict__ eta,
          float* __restrict__ HebbOut, int g)
{
    if (blockIdx.x < NPL_G)
        plastic_body(blockIdx.x, (g + 1) * GB, h0, alpha, Hebb0);
    else
        hebb_body(blockIdx.x - NPL_G, g, Hebb0, h0, eta, HebbOut);
}

// Tail: hebb only (last group)
__global__ __launch_bounds__(256)
void k_hebb(const float* __restrict__ h0, const float* __restrict__ Hebb0,
            const float* __restrict__ eta, float* __restrict__ HebbOut, int g)
{
    hebb_body(blockIdx.x, g, Hebb0, h0, eta, HebbOut);
}

// ---------------------------------------------------------------------------
// Pointwise for one group (GB*Hq elems): gates -> h1, c1, tanh_g
// ---------------------------------------------------------------------------
__global__ __launch_bounds__(256)
void k_pw(const float* __restrict__ c0, const float* __restrict__ bias,
          float* __restrict__ out, int b0)
{
    const int lidx = blockIdx.x * 256 + threadIdx.x;   // 0..GB*Hq-1
    const int b = b0 + (lidx >> 10), h = lidx & 1023;
    const int idx = b * Hq + h;

    float g4[4];
#pragma unroll
    for (int c = 0; c < 4; c++) {
        float v = bias[c * Hq + h];
        int base = b * FOURH + c * Hq + h;
#pragma unroll
        for (int s = 0; s < KSPLIT; s++) v += g_part[s][base];
        g4[c] = v;
    }
    float pl = 0.f;
#pragma unroll
    for (int s = 0; s < PSPLIT; s++)
        pl += g_plastic_part[(size_t)(b * PSPLIT + s) * Hq + h];
    g4[3] += pl;

    float fg = 1.f / (1.f + expf(-g4[0]));
    float ig = 1.f / (1.f + expf(-g4[1]));
    float og = 1.f / (1.f + expf(-g4[2]));
    float tg = tanhf(g4[3]);
    float c1 = fg * c0[idx] + ig * tg;
    float h1 = og * tanhf(c1);

    out[idx]           = h1;  // h1 block
    out[Bq * Hq + idx] = c1;  // c1 block
    g_tanhg[idx] = tg;
}

// ---------------------------------------------------------------------------
// Inputs: x, h0, c0, Hebb0, weight_h, weight_x, bias, alpha, eta
// Output: [h1 (B*H) | c1 (B*H) | Hebb1 (B*H*H)] float32
// ---------------------------------------------------------------------------
extern "C" void kernel_launch(void* const* d_in, const int* in_sizes, int n_in,
                              void* d_out, int out_size)
{
    const float* x     = (const float*)d_in[0];
    const float* h0    = (const float*)d_in[1];
    const float* c0    = (const float*)d_in[2];
    const float* Hebb0 = (const float*)d_in[3];
    const float* Wh    = (const float*)d_in[4];
    const float* Wx    = (const float*)d_in[5];
    const float* bias  = (const float*)d_in[6];
    const float* alpha = (const float*)d_in[7];
    const float* eta   = (const float*)d_in[8];
    float* out = (float*)d_out;
    float* HebbOut = out + 2 * Bq * Hq;

    const int pw_grid = (GB * Hq) / 256;   // 32

    // Pipeline: plastic(g+1) overlaps hebb(g); hebb(g) reads L2-hot slice g.
    k_A<<<NGEMM + NPL_G, 256>>>(x, h0, Wh, Wx, alpha, Hebb0);     // gemm + plastic g0
    k_pw<<<pw_grid, 256>>>(c0, bias, out, 0 * GB);
    k_hp<<<NPL_G + NHB_G, 256>>>(h0, alpha, Hebb0, eta, HebbOut, 0); // hebb g0 + plastic g1
    k_pw<<<pw_grid, 256>>>(c0, bias, out, 1 * GB);
    k_hp<<<NPL_G + NHB_G, 256>>>(h0, alpha, Hebb0, eta, HebbOut, 1); // hebb g1 + plastic g2
    k_pw<<<pw_grid, 256>>>(c0, bias, out, 2 * GB);
    k_hp<<<NPL_G + NHB_G, 256>>>(h0, alpha, Hebb0, eta, HebbOut, 2); // hebb g2 + plastic g3
    k_pw<<<pw_grid, 256>>>(c0, bias, out, 3 * GB);
    k_hebb<<<NHB_G, 256>>>(h0, Hebb0, eta, HebbOut, 3);              // hebb g3
}

// round 13
// speedup vs baseline: 1.3397x; 1.3397x over previous
#include <cuda_runtime.h>
#include <math.h>

// Problem dims
#define Bq      32
#define Dq      512
#define Hq      1024
#define FOURH   4096
#define KTOT    1536            // H + D combined reduction dim
#define KSPLIT  8
#define KCHUNK  (KTOT / KSPLIT) // 192
#define PSPLIT  8               // plastic i-splits per batch
#define PCHUNK  (Hq / PSPLIT)   // 128

#define NPLAST  (Bq * PSPLIT)   // 256 plastic blocks (first in grid)
#define NGEMM   (32 * KSPLIT)   // 256 gemm blocks

// Scratch (static __device__ — no allocation)
__device__ float g_part[KSPLIT][Bq * FOURH];        // GEMM partials (4 MB)
__device__ float g_plastic_part[NPLAST * Hq];       // plastic partials (1 MB)
__device__ float g_tanhg[Bq * Hq];                  // tanh(cell gate) (128 KB)

// ---------------------------------------------------------------------------
// K1 (fused, R2-measured 44.2us): blocks [0,256) plastic, [256,512) gemm.
//
// Plastic (R2-proven body): partial[b,sp,h] = sum_{i in 128-chunk} h0*alpha*Hebb
//   8 float4 loads in flight per 4-row group; gemm branch pins regs=64 which
//   (R6 lesson) is what keeps ptxas from serializing the load batch.
//
// GEMM (R10-proven transposed-A): C[b][j] = sum_k A[k][b]*W[k][j]
// ---------------------------------------------------------------------------
__global__ __launch_bounds__(256)
void fused_k1(const float* __restrict__ x,  const float* __restrict__ h0,
              const float* __restrict__ Wh, const float* __restrict__ Wx,
              const float* __restrict__ alpha, const float* __restrict__ Hebb0)
{
    if (blockIdx.x < NPLAST) {
        // ---------------- plastic partials ----------------
        __shared__ float h0s[PCHUNK];
        const int b  = blockIdx.x >> 3;
        const int sp = blockIdx.x & 7;
        const int i0 = sp * PCHUNK;
        const int tid = threadIdx.x;

        if (tid < PCHUNK) h0s[tid] = h0[b * Hq + i0 + tid];
        __syncthreads();

        const float4* Ap = (const float4*)(alpha + (size_t)i0 * Hq) + tid;
        const float4* Hp = (const float4*)(Hebb0 + (size_t)b * Hq * Hq
                                                 + (size_t)i0 * Hq) + tid;
        const int rs = Hq / 4;  // row stride in float4

        float4 acc = make_float4(0.f, 0.f, 0.f, 0.f);
        for (int i = 0; i < PCHUNK; i += 4) {
            float4 a0 = Ap[(size_t)(i + 0) * rs];
            float4 a1 = Ap[(size_t)(i + 1) * rs];
            float4 a2 = Ap[(size_t)(i + 2) * rs];
            float4 a3 = Ap[(size_t)(i + 3) * rs];
            float4 v0 = Hp[(size_t)(i + 0) * rs];
            float4 v1 = Hp[(size_t)(i + 1) * rs];
            float4 v2 = Hp[(size_t)(i + 2) * rs];
            float4 v3 = Hp[(size_t)(i + 3) * rs];
            float s0 = h0s[i], s1 = h0s[i+1], s2 = h0s[i+2], s3 = h0s[i+3];
            acc.x += s0*a0.x*v0.x; acc.y += s0*a0.y*v0.y; acc.z += s0*a0.z*v0.z; acc.w += s0*a0.w*v0.w;
            acc.x += s1*a1.x*v1.x; acc.y += s1*a1.y*v1.y; acc.z += s1*a1.z*v1.z; acc.w += s1*a1.w*v1.w;
            acc.x += s2*a2.x*v2.x; acc.y += s2*a2.y*v2.y; acc.z += s2*a2.z*v2.z; acc.w += s2*a2.w*v2.w;
            acc.x += s3*a3.x*v3.x; acc.y += s3*a3.y*v3.y; acc.z += s3*a3.z*v3.z; acc.w += s3*a3.w*v3.w;
        }
        float4* outp = (float4*)(g_plastic_part + (size_t)blockIdx.x * Hq);
        outp[tid] = acc;
    } else {
        // ---------------- gemm partials (transposed-A, R10) ----------------
        __shared__ float Ws[32][128];
        __shared__ float As[32][33];   // [b][k], padded

        const int gid = blockIdx.x - NPLAST;
        const int jt  = gid & 31;       // j tile (128 wide)
        const int ks  = gid >> 5;       // k split (0..7)
        const int tid = threadIdx.x;
        const int tj  = tid & 31;
        const int tb  = tid >> 5;

        float acc[4][4];
#pragma unroll
        for (int i = 0; i < 4; i++)
#pragma unroll
            for (int j = 0; j < 4; j++) acc[i][j] = 0.f;

        const int k0base = ks * KCHUNK;
        const int jbase  = jt * 128;

        const float4* Wh4 = (const float4*)Wh;   // row stride 1024 float4
        const float4* Wx4 = (const float4*)Wx;

        for (int t = 0; t < KCHUNK / 32; t++) {
            const int k0 = k0base + t * 32;
            __syncthreads();
#pragma unroll
            for (int s = 0; s < 4; s++) {
                int lin = s * 256 + tid;
                int kk = lin >> 5, j4 = lin & 31;
                int k = k0 + kk;
                float4 w = (k < Hq) ? Wh4[(size_t)k * 1024 + (jbase >> 2) + j4]
                                    : Wx4[(size_t)(k - Hq) * 1024 + (jbase >> 2) + j4];
                *(float4*)&Ws[kk][j4 * 4] = w;
            }
#pragma unroll
            for (int s = 0; s < 4; s++) {
                int lin = s * 256 + tid;
                int bb = lin >> 5, kk = lin & 31;
                int k = k0 + kk;
                As[bb][kk] = (k < Hq) ? h0[bb * Hq + k] : x[bb * Dq + (k - Hq)];
            }
            __syncthreads();
#pragma unroll
            for (int kk = 0; kk < 32; kk++) {
                float4 w = *(const float4*)&Ws[kk][tj * 4];
                float a0 = As[tb * 4 + 0][kk];
                float a1 = As[tb * 4 + 1][kk];
                float a2 = As[tb * 4 + 2][kk];
                float a3 = As[tb * 4 + 3][kk];
                acc[0][0] += a0*w.x; acc[0][1] += a0*w.y; acc[0][2] += a0*w.z; acc[0][3] += a0*w.w;
                acc[1][0] += a1*w.x; acc[1][1] += a1*w.y; acc[1][2] += a1*w.z; acc[1][3] += a1*w.w;
                acc[2][0] += a2*w.x; acc[2][1] += a2*w.y; acc[2][2] += a2*w.z; acc[2][3] += a2*w.w;
                acc[3][0] += a3*w.x; acc[3][1] += a3*w.y; acc[3][2] += a3*w.z; acc[3][3] += a3*w.w;
            }
        }

        float* outp = g_part[ks];
#pragma unroll
        for (int bb = 0; bb < 4; bb++) {
            int b = tb * 4 + bb;
            int base = b * FOURH + jbase + tj * 4;
            *(float4*)&outp[base] = make_float4(acc[bb][0], acc[bb][1], acc[bb][2], acc[bb][3]);
        }
    }
}

// ---------------------------------------------------------------------------
// K2: pointwise gates -> h1, c1, tanh_g  (R2-proven, 8+8 partials)
// ---------------------------------------------------------------------------
__global__ __launch_bounds__(256)
void pointwise_kernel(const float* __restrict__ c0, const float* __restrict__ bias,
                      float* __restrict__ out)
{
    const int idx = blockIdx.x * 256 + threadIdx.x;   // 0..32767
    const int b = idx >> 10, h = idx & 1023;

    float g4[4];
#pragma unroll
    for (int c = 0; c < 4; c++) {
        float v = bias[c * Hq + h];
        int base = b * FOURH + c * Hq + h;
#pragma unroll
        for (int s = 0; s < KSPLIT; s++) v += g_part[s][base];
        g4[c] = v;
    }
    float pl = 0.f;
#pragma unroll
    for (int s = 0; s < PSPLIT; s++)
        pl += g_plastic_part[(size_t)(b * PSPLIT + s) * Hq + h];
    g4[3] += pl;

    float fg = 1.f / (1.f + expf(-g4[0]));
    float ig = 1.f / (1.f + expf(-g4[1]));
    float og = 1.f / (1.f + expf(-g4[2]));
    float tg = tanhf(g4[3]);
    float c1 = fg * c0[idx] + ig * tg;
    float h1 = og * tanhf(c1);

    out[idx]           = h1;  // h1 block
    out[Bq * Hq + idx] = c1;  // c1 block
    g_tanhg[idx] = tg;
}

// ---------------------------------------------------------------------------
// K3: Hebb1[b,h,i] = clip(Hebb0[b,h,i] + eta*h0[b,h]*tanh_g[b,i], -1, 1)
// R8-proven 4-row version (measured 36.4us, 74% DRAM). Reversed order: the
// plastic pass ends on high-b slices, reversed hebb re-reads them from L2.
// ---------------------------------------------------------------------------
__global__ __launch_bounds__(256)
void hebb_kernel(const float* __restrict__ Hebb0, const float* __restrict__ h0,
                 const float* __restrict__ eta, float* __restrict__ HebbOut)
{
    const int r0 = (Bq * Hq - 4) - blockIdx.x * 4;   // reversed, 4-row group
    const int b  = r0 >> 10;
    const float e = eta[0];
    const int t = threadIdx.x;

    float4 tv = ((const float4*)(g_tanhg + (size_t)b * Hq))[t];

    const float4* in4 = (const float4*)(Hebb0   + (size_t)r0 * Hq) + t;
    float4*       o4  = (float4*)      (HebbOut + (size_t)r0 * Hq) + t;

    float c0f = e * h0[r0 + 0];
    float c1f = e * h0[r0 + 1];
    float c2f = e * h0[r0 + 2];
    float c3f = e * h0[r0 + 3];

    float4 v0 = __ldcs(in4 + 0 * 256);
    float4 v1 = __ldcs(in4 + 1 * 256);
    float4 v2 = __ldcs(in4 + 2 * 256);
    float4 v3 = __ldcs(in4 + 3 * 256);

    float4 o;
    o.x = fminf(1.f, fmaxf(-1.f, fmaf(c0f, tv.x, v0.x)));
    o.y = fminf(1.f, fmaxf(-1.f, fmaf(c0f, tv.y, v0.y)));
    o.z = fminf(1.f, fmaxf(-1.f, fmaf(c0f, tv.z, v0.z)));
    o.w = fminf(1.f, fmaxf(-1.f, fmaf(c0f, tv.w, v0.w)));
    __stcs(o4 + 0 * 256, o);
    o.x = fminf(1.f, fmaxf(-1.f, fmaf(c1f, tv.x, v1.x)));
    o.y = fminf(1.f, fmaxf(-1.f, fmaf(c1f, tv.y, v1.y)));
    o.z = fminf(1.f, fmaxf(-1.f, fmaf(c1f, tv.z, v1.z)));
    o.w = fminf(1.f, fmaxf(-1.f, fmaf(c1f, tv.w, v1.w)));
    __stcs(o4 + 1 * 256, o);
    o.x = fminf(1.f, fmaxf(-1.f, fmaf(c2f, tv.x, v2.x)));
    o.y = fminf(1.f, fmaxf(-1.f, fmaf(c2f, tv.y, v2.y)));
    o.z = fminf(1.f, fmaxf(-1.f, fmaf(c2f, tv.z, v2.z)));
    o.w = fminf(1.f, fmaxf(-1.f, fmaf(c2f, tv.w, v2.w)));
    __stcs(o4 + 2 * 256, o);
    o.x = fminf(1.f, fmaxf(-1.f, fmaf(c3f, tv.x, v3.x)));
    o.y = fminf(1.f, fmaxf(-1.f, fmaf(c3f, tv.y, v3.y)));
    o.z = fminf(1.f, fmaxf(-1.f, fmaf(c3f, tv.z, v3.z)));
    o.w = fminf(1.f, fmaxf(-1.f, fmaf(c3f, tv.w, v3.w)));
    __stcs(o4 + 3 * 256, o);
}

// ---------------------------------------------------------------------------
// Inputs: x, h0, c0, Hebb0, weight_h, weight_x, bias, alpha, eta
// Output: [h1 (B*H) | c1 (B*H) | Hebb1 (B*H*H)] float32
// ---------------------------------------------------------------------------
extern "C" void kernel_launch(void* const* d_in, const int* in_sizes, int n_in,
                              void* d_out, int out_size)
{
    const float* x     = (const float*)d_in[0];
    const float* h0    = (const float*)d_in[1];
    const float* c0    = (const float*)d_in[2];
    const float* Hebb0 = (const float*)d_in[3];
    const float* Wh    = (const float*)d_in[4];
    const float* Wx    = (const float*)d_in[5];
    const float* bias  = (const float*)d_in[6];
    const float* alpha = (const float*)d_in[7];
    const float* eta   = (const float*)d_in[8];
    float* out = (float*)d_out;

    fused_k1<<<NPLAST + NGEMM, 256>>>(x, h0, Wh, Wx, alpha, Hebb0);
    pointwise_kernel<<<(Bq * Hq) / 256, 256>>>(c0, bias, out);
    hebb_kernel<<<(Bq * Hq) / 4, 256>>>(Hebb0, h0, eta, out + 2 * Bq * Hq);
}